// round 16
// baseline (speedup 1.0000x reference)
#include <cuda_runtime.h>
#include <cuda_bf16.h>
#include <cstdint>

constexpr int NN   = 50000;   // nodes
constexpr int NE   = 600000;  // edges
constexpr int FEAT = 256;
constexpr int HID  = 128;
constexpr int CLS  = 32;

// ---------------- device scratch (no allocs allowed) ----------------
__device__ float g_yA[NN * HID];
__device__ float g_zA[NN * HID];
__device__ float g_yB[NN * HID];
__device__ float g_zB[NN * HID];
__device__ float g_fg[NN * 64];
__device__ int   g_off[NN + 1];
__device__ int   g_cur[NN];
__device__ int   g_csr[NE];

constexpr int SCAN_BLK = 512;
constexpr int SCAN_N   = NN + 1;
constexpr int SCAN_NB  = (SCAN_N + SCAN_BLK - 1) / SCAN_BLK;      // 98
__device__ int g_bsum[SCAN_NB];

__device__ __nv_bfloat16 g_xh[NN * HID];
__device__ __nv_bfloat16 g_xl[NN * HID];
__device__ __nv_bfloat16 g_ewh[128 * 256];
__device__ __nv_bfloat16 g_ewl[128 * 256];
__device__ __nv_bfloat16 g_rwh[3 * 128 * 128];
__device__ __nv_bfloat16 g_rwl[3 * 128 * 128];
__device__ __nv_bfloat16 g_owh[3 * 128 * 128];
__device__ __nv_bfloat16 g_owl[3 * 128 * 128];
__device__ __nv_bfloat16 g_hwh[64 * 128];     // head weights packed, ^T, split
__device__ __nv_bfloat16 g_hwl[64 * 128];

// ---------------- helpers ----------------
__device__ __forceinline__ uint32_t smem_u32(const void* p) {
    uint32_t a;
    asm("{ .reg .u64 t; cvta.to.shared.u64 t, %1; cvt.u32.u64 %0, t; }" : "=r"(a) : "l"(p));
    return a;
}
__device__ __forceinline__ void split2(float v, __nv_bfloat16& h, __nv_bfloat16& l) {
    h = __float2bfloat16_rn(v);
    l = __float2bfloat16_rn(v - __bfloat162float(h));
}
__device__ __forceinline__ void ldsm4(uint32_t* r, uint32_t addr) {
    asm volatile("ldmatrix.sync.aligned.m8n8.x4.shared.b16 {%0,%1,%2,%3}, [%4];"
        : "=r"(r[0]), "=r"(r[1]), "=r"(r[2]), "=r"(r[3]) : "r"(addr));
}
__device__ __forceinline__ void ldsm2(uint32_t* r, uint32_t addr) {
    asm volatile("ldmatrix.sync.aligned.m8n8.x2.shared.b16 {%0,%1}, [%2];"
        : "=r"(r[0]), "=r"(r[1]) : "r"(addr));
}
__device__ __forceinline__ void mma_bf16(float* c, const uint32_t* a, const uint32_t* b) {
    asm volatile(
        "mma.sync.aligned.m16n8k16.row.col.f32.bf16.bf16.f32 "
        "{%0,%1,%2,%3}, {%4,%5,%6,%7}, {%8,%9}, {%0,%1,%2,%3};"
        : "+f"(c[0]), "+f"(c[1]), "+f"(c[2]), "+f"(c[3])
        : "r"(a[0]), "r"(a[1]), "r"(a[2]), "r"(a[3]), "r"(b[0]), "r"(b[1]));
}

constexpr int KCH  = 128;
constexpr int KST  = KCH + 8;
constexpr int TILE_ELEMS = 128 * KST;          // 17408 bf16
constexpr int TILE_BYTES = TILE_ELEMS * 2;     // 34816
constexpr int WTILE_ELEMS = 64 * KST;          // head W tile (64 rows)
constexpr int GSM_SIZE = 4 * TILE_BYTES;                       // emb
constexpr int LSM_SIZE = 6 * TILE_BYTES;                       // fused layer (204KB)
constexpr int HSM_SIZE = 2 * TILE_BYTES + 2 * WTILE_ELEMS * 2; // fused head (~102KB)

// ---------------------------------------------------------------------------
// CSR aggregate of one node into registers: relu(z[n] + sum y[csr])
// ---------------------------------------------------------------------------
__device__ __forceinline__ float4 agg_node(const float4* __restrict__ y4,
                                           const float4* __restrict__ z4,
                                           const int* __restrict__ csr,
                                           int node, int lane, int s, int e)
{
    float4 acc = z4[(size_t)node * 32 + lane];
    for (int b = s; b < e; b += 32) {
        int idx = b + lane;
        int mysrc = (idx < e) ? csr[idx] : 0;
        int cnt = e - b; if (cnt > 32) cnt = 32;
        int j = 0;
        for (; j + 4 <= cnt; j += 4) {
            int s0 = __shfl_sync(0xffffffffu, mysrc, j);
            int s1 = __shfl_sync(0xffffffffu, mysrc, j + 1);
            int s2 = __shfl_sync(0xffffffffu, mysrc, j + 2);
            int s3 = __shfl_sync(0xffffffffu, mysrc, j + 3);
            float4 v0 = y4[(size_t)s0 * 32 + lane];
            float4 v1 = y4[(size_t)s1 * 32 + lane];
            float4 v2 = y4[(size_t)s2 * 32 + lane];
            float4 v3 = y4[(size_t)s3 * 32 + lane];
            acc.x += (v0.x + v1.x) + (v2.x + v3.x);
            acc.y += (v0.y + v1.y) + (v2.y + v3.y);
            acc.z += (v0.z + v1.z) + (v2.z + v3.z);
            acc.w += (v0.w + v1.w) + (v2.w + v3.w);
        }
        for (; j < cnt; j++) {
            int s0 = __shfl_sync(0xffffffffu, mysrc, j);
            float4 v0 = y4[(size_t)s0 * 32 + lane];
            acc.x += v0.x; acc.y += v0.y; acc.z += v0.z; acc.w += v0.w;
        }
    }
    acc.x = fmaxf(acc.x, 0.f); acc.y = fmaxf(acc.y, 0.f);
    acc.z = fmaxf(acc.z, 0.f); acc.w = fmaxf(acc.w, 0.f);
    return acc;
}

// aggregate 128 rows of this CTA into split-bf16 smem A tiles
__device__ __forceinline__ void agg_tile_to_smem(const float4* __restrict__ yIn,
                                                 const float4* __restrict__ zIn,
                                                 const int* __restrict__ off,
                                                 const int* __restrict__ csr,
                                                 __nv_bfloat16* sAh, __nv_bfloat16* sAl,
                                                 int row0, int warp, int lane)
{
#pragma unroll 1
    for (int it = 0; it < 16; it++) {
        int r = it * 8 + warp;
        int node = row0 + r;
        float4 acc = make_float4(0.f, 0.f, 0.f, 0.f);
        if (node < NN)
            acc = agg_node(yIn, zIn, csr, node, lane, off[node], off[node + 1]);
        __nv_bfloat16 h0, l0, h1, l1, h2, l2, h3, l3;
        split2(acc.x, h0, l0); split2(acc.y, h1, l1);
        split2(acc.z, h2, l2); split2(acc.w, h3, l3);
        __nv_bfloat162 ha, hb, la, lb;
        ha.x = h0; ha.y = h1; hb.x = h2; hb.y = h3;
        la.x = l0; la.y = l1; lb.x = l2; lb.y = l3;
        int base = r * KST + lane * 4;
        *(__nv_bfloat162*)(sAh + base)     = ha;
        *(__nv_bfloat162*)(sAh + base + 2) = hb;
        *(__nv_bfloat162*)(sAl + base)     = la;
        *(__nv_bfloat162*)(sAl + base + 2) = lb;
    }
}

// ---------------------------------------------------------------------------
// Layer GEMM from explicit split-bf16 input (layer 0 only)
// ---------------------------------------------------------------------------
__device__ __forceinline__ void layer_mma_epilogue(
    __nv_bfloat16* sAh, __nv_bfloat16* sAl,
    __nv_bfloat16* sRh, __nv_bfloat16* sRl,
    __nv_bfloat16* sOh, __nv_bfloat16* sOl,
    const float* __restrict__ bias,
    float* __restrict__ outY, float* __restrict__ outZ,
    int row0, int warp, int lane)
{
    const int wm = (warp >> 1) * 32;
    const int wn = (warp & 1) * 64;

    float accY[2][8][4], accZ[2][8][4];
#pragma unroll
    for (int m = 0; m < 2; m++)
#pragma unroll
        for (int nt = 0; nt < 8; nt++)
#pragma unroll
            for (int j = 0; j < 4; j++) { accY[m][nt][j] = 0.f; accZ[m][nt][j] = 0.f; }

    const uint32_t uAh = smem_u32(sAh), uAl = smem_u32(sAl);
    const uint32_t uRh = smem_u32(sRh), uRl = smem_u32(sRl);
    const uint32_t uOh = smem_u32(sOh), uOl = smem_u32(sOl);

    const int rin  = lane & 7;
    const int quad = lane >> 3;
    const int a_radd = (quad & 1) * 8 + rin;
    const int a_cadd = (quad >> 1) * 16;
    const int b_l16  = lane & 15;
    const int b_radd = b_l16 & 7;
    const int b_cadd = (b_l16 >> 3) * 16;

#pragma unroll
    for (int ks = 0; ks < 8; ks++) {
        uint32_t afh[2][4], afl[2][4];
#pragma unroll
        for (int m = 0; m < 2; m++) {
            uint32_t off = (uint32_t)(wm + m * 16 + a_radd) * (KST * 2)
                         + (uint32_t)(ks * 32 + a_cadd);
            ldsm4(afh[m], uAh + off);
            ldsm4(afl[m], uAl + off);
        }
#pragma unroll
        for (int nt = 0; nt < 8; nt++) {
            uint32_t off = (uint32_t)(wn + nt * 8 + b_radd) * (KST * 2)
                         + (uint32_t)(ks * 32 + b_cadd);
            uint32_t rh[2], rl[2], oh[2], ol[2];
            ldsm2(rh, uRh + off);
            ldsm2(rl, uRl + off);
            ldsm2(oh, uOh + off);
            ldsm2(ol, uOl + off);
#pragma unroll
            for (int m = 0; m < 2; m++) {
                mma_bf16(accY[m][nt], afh[m], rh);
                mma_bf16(accY[m][nt], afl[m], rh);
                mma_bf16(accY[m][nt], afh[m], rl);
                mma_bf16(accZ[m][nt], afh[m], oh);
                mma_bf16(accZ[m][nt], afl[m], oh);
                mma_bf16(accZ[m][nt], afh[m], ol);
            }
        }
    }

    const int g = lane >> 2, tig = lane & 3;
#pragma unroll
    for (int m = 0; m < 2; m++) {
#pragma unroll
        for (int nt = 0; nt < 8; nt++) {
            int col = wn + nt * 8 + 2 * tig;
            int r1 = row0 + wm + m * 16 + g;
            int r2 = r1 + 8;
            float b0 = bias[col], b1 = bias[col + 1];
            if (r1 < NN) {
                *(float2*)(outY + (size_t)r1 * 128 + col) =
                    make_float2(accY[m][nt][0], accY[m][nt][1]);
                *(float2*)(outZ + (size_t)r1 * 128 + col) =
                    make_float2(accZ[m][nt][0] + b0, accZ[m][nt][1] + b1);
            }
            if (r2 < NN) {
                *(float2*)(outY + (size_t)r2 * 128 + col) =
                    make_float2(accY[m][nt][2], accY[m][nt][3]);
                *(float2*)(outZ + (size_t)r2 * 128 + col) =
                    make_float2(accZ[m][nt][2] + b0, accZ[m][nt][3] + b1);
            }
        }
    }
}

__device__ __forceinline__ void stage_layer_weights(
    const __nv_bfloat16* __restrict__ Rh, const __nv_bfloat16* __restrict__ Rl,
    const __nv_bfloat16* __restrict__ Oh, const __nv_bfloat16* __restrict__ Ol,
    __nv_bfloat16* sRh, __nv_bfloat16* sRl, __nv_bfloat16* sOh, __nv_bfloat16* sOl,
    int tid)
{
#pragma unroll
    for (int v = 0; v < 8; v++) {
        int i = tid + v * 256;
        int r = i >> 4, c = (i & 15) * 8;
        *(uint4*)(sRh + r * KST + c) = *(const uint4*)(Rh + (size_t)r * 128 + c);
        *(uint4*)(sRl + r * KST + c) = *(const uint4*)(Rl + (size_t)r * 128 + c);
        *(uint4*)(sOh + r * KST + c) = *(const uint4*)(Oh + (size_t)r * 128 + c);
        *(uint4*)(sOl + r * KST + c) = *(const uint4*)(Ol + (size_t)r * 128 + c);
    }
}

// Layer 0: A from global split-bf16 (emb output)
__global__ void __launch_bounds__(256)
gemm_layer0(const __nv_bfloat16* __restrict__ Ah, const __nv_bfloat16* __restrict__ Al,
            const __nv_bfloat16* __restrict__ Rh, const __nv_bfloat16* __restrict__ Rl,
            const __nv_bfloat16* __restrict__ Oh, const __nv_bfloat16* __restrict__ Ol,
            const float* __restrict__ bias,
            float* __restrict__ outY, float* __restrict__ outZ)
{
    extern __shared__ __nv_bfloat16 sm[];
    __nv_bfloat16* sAh = sm;
    __nv_bfloat16* sAl = sm + TILE_ELEMS;
    __nv_bfloat16* sRh = sm + 2 * TILE_ELEMS;
    __nv_bfloat16* sRl = sm + 3 * TILE_ELEMS;
    __nv_bfloat16* sOh = sm + 4 * TILE_ELEMS;
    __nv_bfloat16* sOl = sm + 5 * TILE_ELEMS;

    const int tid = threadIdx.x;
    const int warp = tid >> 5, lane = tid & 31;
    const int row0 = blockIdx.x * 128;
    const int rows = NN - row0;

    stage_layer_weights(Rh, Rl, Oh, Ol, sRh, sRl, sOh, sOl, tid);
#pragma unroll
    for (int v = 0; v < 8; v++) {
        int i = tid + v * 256;
        int r = i >> 4, c = (i & 15) * 8;
        uint4 t = make_uint4(0u, 0u, 0u, 0u);
        uint4 u = make_uint4(0u, 0u, 0u, 0u);
        if (r < rows) {
            t = *(const uint4*)(Ah + (size_t)(row0 + r) * 128 + c);
            u = *(const uint4*)(Al + (size_t)(row0 + r) * 128 + c);
        }
        *(uint4*)(sAh + r * KST + c) = t;
        *(uint4*)(sAl + r * KST + c) = u;
    }
    __syncthreads();
    layer_mma_epilogue(sAh, sAl, sRh, sRl, sOh, sOl, bias, outY, outZ, row0, warp, lane);
}

// Layers 1,2: A produced in-kernel from CSR aggregation of (yIn, zIn)
__global__ void __launch_bounds__(256)
gemm_layer_fused(const float4* __restrict__ yIn, const float4* __restrict__ zIn,
                 const int* __restrict__ off, const int* __restrict__ csr,
                 const __nv_bfloat16* __restrict__ Rh, const __nv_bfloat16* __restrict__ Rl,
                 const __nv_bfloat16* __restrict__ Oh, const __nv_bfloat16* __restrict__ Ol,
                 const float* __restrict__ bias,
                 float* __restrict__ outY, float* __restrict__ outZ)
{
    extern __shared__ __nv_bfloat16 sm[];
    __nv_bfloat16* sAh = sm;
    __nv_bfloat16* sAl = sm + TILE_ELEMS;
    __nv_bfloat16* sRh = sm + 2 * TILE_ELEMS;
    __nv_bfloat16* sRl = sm + 3 * TILE_ELEMS;
    __nv_bfloat16* sOh = sm + 4 * TILE_ELEMS;
    __nv_bfloat16* sOl = sm + 5 * TILE_ELEMS;

    const int tid = threadIdx.x;
    const int warp = tid >> 5, lane = tid & 31;
    const int row0 = blockIdx.x * 128;

    stage_layer_weights(Rh, Rl, Oh, Ol, sRh, sRl, sOh, sOl, tid);
    agg_tile_to_smem(yIn, zIn, off, csr, sAh, sAl, row0, warp, lane);
    __syncthreads();
    layer_mma_epilogue(sAh, sAl, sRh, sRl, sOh, sOl, bias, outY, outZ, row0, warp, lane);
}

// Head: aggregate + head GEMM (N=64) -> fg
__global__ void __launch_bounds__(256)
gemm_head_fused(const float4* __restrict__ yIn, const float4* __restrict__ zIn,
                const int* __restrict__ off, const int* __restrict__ csr,
                const __nv_bfloat16* __restrict__ Wh, const __nv_bfloat16* __restrict__ Wl,
                float* __restrict__ fg)
{
    extern __shared__ __nv_bfloat16 sm[];
    __nv_bfloat16* sAh = sm;
    __nv_bfloat16* sAl = sm + TILE_ELEMS;
    __nv_bfloat16* sWh = sm + 2 * TILE_ELEMS;
    __nv_bfloat16* sWl = sm + 2 * TILE_ELEMS + WTILE_ELEMS;

    const int tid = threadIdx.x;
    const int warp = tid >> 5, lane = tid & 31;
    const int row0 = blockIdx.x * 128;

    // stage head weights [64,128]
#pragma unroll
    for (int v = 0; v < 4; v++) {
        int i = tid + v * 256;
        int r = i >> 4, c = (i & 15) * 8;
        *(uint4*)(sWh + r * KST + c) = *(const uint4*)(Wh + (size_t)r * 128 + c);
        *(uint4*)(sWl + r * KST + c) = *(const uint4*)(Wl + (size_t)r * 128 + c);
    }
    agg_tile_to_smem(yIn, zIn, off, csr, sAh, sAl, row0, warp, lane);
    __syncthreads();

    const int wm = (warp >> 1) * 32;
    const int wn = (warp & 1) * 32;      // N=64 split over 2 warp columns

    float acc[2][4][4];
#pragma unroll
    for (int m = 0; m < 2; m++)
#pragma unroll
        for (int nt = 0; nt < 4; nt++)
#pragma unroll
            for (int j = 0; j < 4; j++) acc[m][nt][j] = 0.f;

    const uint32_t uAh = smem_u32(sAh), uAl = smem_u32(sAl);
    const uint32_t uWh = smem_u32(sWh), uWl = smem_u32(sWl);

    const int rin  = lane & 7;
    const int quad = lane >> 3;
    const int a_radd = (quad & 1) * 8 + rin;
    const int a_cadd = (quad >> 1) * 16;
    const int b_l16  = lane & 15;
    const int b_radd = b_l16 & 7;
    const int b_cadd = (b_l16 >> 3) * 16;

#pragma unroll
    for (int ks = 0; ks < 8; ks++) {
        uint32_t afh[2][4], afl[2][4];
#pragma unroll
        for (int m = 0; m < 2; m++) {
            uint32_t off2 = (uint32_t)(wm + m * 16 + a_radd) * (KST * 2)
                          + (uint32_t)(ks * 32 + a_cadd);
            ldsm4(afh[m], uAh + off2);
            ldsm4(afl[m], uAl + off2);
        }
#pragma unroll
        for (int nt = 0; nt < 4; nt++) {
            uint32_t off2 = (uint32_t)(wn + nt * 8 + b_radd) * (KST * 2)
                          + (uint32_t)(ks * 32 + b_cadd);
            uint32_t wh[2], wl[2];
            ldsm2(wh, uWh + off2);
            ldsm2(wl, uWl + off2);
#pragma unroll
            for (int m = 0; m < 2; m++) {
                mma_bf16(acc[m][nt], afh[m], wh);
                mma_bf16(acc[m][nt], afl[m], wh);
                mma_bf16(acc[m][nt], afh[m], wl);
            }
        }
    }

    const int g = lane >> 2, tig = lane & 3;
#pragma unroll
    for (int m = 0; m < 2; m++) {
#pragma unroll
        for (int nt = 0; nt < 4; nt++) {
            int col = wn + nt * 8 + 2 * tig;
            int r1 = row0 + wm + m * 16 + g;
            int r2 = r1 + 8;
            if (r1 < NN)
                *(float2*)(fg + (size_t)r1 * 64 + col) = make_float2(acc[m][nt][0], acc[m][nt][1]);
            if (r2 < NN)
                *(float2*)(fg + (size_t)r2 * 64 + col) = make_float2(acc[m][nt][2], acc[m][nt][3]);
        }
    }
}

// ---------------------------------------------------------------------------
// Embedding GEMM (split bf16 mma.sync, K=256 in 2 chunks)
// ---------------------------------------------------------------------------
__global__ void __launch_bounds__(256)
gemm_emb(const float* __restrict__ A,
         const __nv_bfloat16* __restrict__ Bh, const __nv_bfloat16* __restrict__ Bl,
         const float* __restrict__ bias,
         __nv_bfloat16* __restrict__ outH, __nv_bfloat16* __restrict__ outL)
{
    extern __shared__ __nv_bfloat16 sm[];
    __nv_bfloat16* sAh = sm;
    __nv_bfloat16* sAl = sm + TILE_ELEMS;
    __nv_bfloat16* sBh = sm + 2 * TILE_ELEMS;
    __nv_bfloat16* sBl = sm + 3 * TILE_ELEMS;

    const int tid  = threadIdx.x;
    const int warp = tid >> 5, lane = tid & 31;
    const int row0 = blockIdx.x * 128;
    const int rows = NN - row0;
    const int wm = (warp >> 1) * 32;
    const int wn = (warp & 1) * 64;
    const int K = 256;

    float acc[2][8][4];
#pragma unroll
    for (int m = 0; m < 2; m++)
#pragma unroll
        for (int nt = 0; nt < 8; nt++)
#pragma unroll
            for (int j = 0; j < 4; j++) acc[m][nt][j] = 0.f;

    const uint32_t uAh = smem_u32(sAh), uAl = smem_u32(sAl);
    const uint32_t uBh = smem_u32(sBh), uBl = smem_u32(sBl);

    const int rin  = lane & 7;
    const int quad = lane >> 3;
    const int a_radd = (quad & 1) * 8 + rin;
    const int a_cadd = (quad >> 1) * 16;
    const int b_l16  = lane & 15;
    const int b_radd = b_l16 & 7;
    const int b_cadd = (b_l16 >> 3) * 16;

    for (int kc = 0; kc < K; kc += KCH) {
        if (kc) __syncthreads();
#pragma unroll
        for (int v = 0; v < 16; v++) {
            int i = tid + v * 256;
            int r = i >> 5, c4 = (i & 31) * 4;
            float4 t = make_float4(0.f, 0.f, 0.f, 0.f);
            if (r < rows)
                t = *(const float4*)(A + (size_t)(row0 + r) * K + kc + c4);
            __nv_bfloat16 h0, l0, h1, l1, h2, l2, h3, l3;
            split2(t.x, h0, l0); split2(t.y, h1, l1);
            split2(t.z, h2, l2); split2(t.w, h3, l3);
            __nv_bfloat162 ha, hb, la, lb;
            ha.x = h0; ha.y = h1; hb.x = h2; hb.y = h3;
            la.x = l0; la.y = l1; lb.x = l2; lb.y = l3;
            *(__nv_bfloat162*)(sAh + r * KST + c4)     = ha;
            *(__nv_bfloat162*)(sAh + r * KST + c4 + 2) = hb;
            *(__nv_bfloat162*)(sAl + r * KST + c4)     = la;
            *(__nv_bfloat162*)(sAl + r * KST + c4 + 2) = lb;
        }
#pragma unroll
        for (int v = 0; v < 8; v++) {
            int i = tid + v * 256;
            int r = i >> 4, c = (i & 15) * 8;
            *(uint4*)(sBh + r * KST + c) = *(const uint4*)(Bh + (size_t)r * K + kc + c);
            *(uint4*)(sBl + r * KST + c) = *(const uint4*)(Bl + (size_t)r * K + kc + c);
        }
        __syncthreads();

#pragma unroll
        for (int ks = 0; ks < 8; ks++) {
            uint32_t afh[2][4], afl[2][4];
#pragma unroll
            for (int m = 0; m < 2; m++) {
                uint32_t off = (uint32_t)(wm + m * 16 + a_radd) * (KST * 2)
                             + (uint32_t)(ks * 32 + a_cadd);
                ldsm4(afh[m], uAh + off);
                ldsm4(afl[m], uAl + off);
            }
#pragma unroll
            for (int nt = 0; nt < 8; nt++) {
                uint32_t bh[2], bl[2];
                uint32_t off = (uint32_t)(wn + nt * 8 + b_radd) * (KST * 2)
                             + (uint32_t)(ks * 32 + b_cadd);
                ldsm2(bh, uBh + off);
                ldsm2(bl, uBl + off);
#pragma unroll
                for (int m = 0; m < 2; m++) {
                    mma_bf16(acc[m][nt], afh[m], bh);
                    mma_bf16(acc[m][nt], afl[m], bh);
                    mma_bf16(acc[m][nt], afh[m], bl);
                }
            }
        }
    }

    const int g = lane >> 2, tig = lane & 3;
#pragma unroll
    for (int m = 0; m < 2; m++) {
#pragma unroll
        for (int nt = 0; nt < 8; nt++) {
            int col = wn + nt * 8 + 2 * tig;
            int r1 = row0 + wm + m * 16 + g;
            int r2 = r1 + 8;
            float b0 = bias[col], b1 = bias[col + 1];
            float v00 = fmaxf(acc[m][nt][0] + b0, 0.f), v01 = fmaxf(acc[m][nt][1] + b1, 0.f);
            float v10 = fmaxf(acc[m][nt][2] + b0, 0.f), v11 = fmaxf(acc[m][nt][3] + b1, 0.f);
            __nv_bfloat16 h0, l0, h1, l1;
            if (r1 < NN) {
                split2(v00, h0, l0); split2(v01, h1, l1);
                __nv_bfloat162 hh; hh.x = h0; hh.y = h1;
                __nv_bfloat162 ll; ll.x = l0; ll.y = l1;
                *(__nv_bfloat162*)(outH + (size_t)r1 * 128 + col) = hh;
                *(__nv_bfloat162*)(outL + (size_t)r1 * 128 + col) = ll;
            }
            if (r2 < NN) {
                split2(v10, h0, l0); split2(v11, h1, l1);
                __nv_bfloat162 hh; hh.x = h0; hh.y = h1;
                __nv_bfloat162 ll; ll.x = l0; ll.y = l1;
                *(__nv_bfloat162*)(outH + (size_t)r2 * 128 + col) = hh;
                *(__nv_bfloat162*)(outL + (size_t)r2 * 128 + col) = ll;
            }
        }
    }
}

// ---------------------------------------------------------------------------
// One-shot weight prep (now head weights -> packed^T split bf16)
// ---------------------------------------------------------------------------
constexpr int PW_EMB  = 256 * 128;
constexpr int PW_REL  = 3 * 128 * 128;
constexpr int PW_HEAD = 64 * 128;
constexpr int PW_TOTAL = PW_EMB + 2 * PW_REL + PW_HEAD;

__global__ void prep_weights(const float* __restrict__ emb_w,
                             const float* __restrict__ rel_w,
                             const float* __restrict__ root_w,
                             const float* __restrict__ head_w,
                             __nv_bfloat16* __restrict__ ewh, __nv_bfloat16* __restrict__ ewl,
                             __nv_bfloat16* __restrict__ rwh, __nv_bfloat16* __restrict__ rwl,
                             __nv_bfloat16* __restrict__ owh, __nv_bfloat16* __restrict__ owl,
                             __nv_bfloat16* __restrict__ hwh, __nv_bfloat16* __restrict__ hwl)
{
    int i = blockIdx.x * blockDim.x + threadIdx.x;
    if (i >= PW_TOTAL) return;
    if (i < PW_EMB) {
        int k = i / 128, n = i % 128;
        __nv_bfloat16 h, l;
        split2(emb_w[i], h, l);
        ewh[n * 256 + k] = h;
        ewl[n * 256 + k] = l;
    } else if (i < PW_EMB + PW_REL) {
        int r = i - PW_EMB;
        int l0 = r / (128 * 128), rem = r % (128 * 128);
        int k = rem / 128, n = rem % 128;
        __nv_bfloat16 h, lo;
        split2(rel_w[r], h, lo);
        rwh[(size_t)l0 * 128 * 128 + n * 128 + k] = h;
        rwl[(size_t)l0 * 128 * 128 + n * 128 + k] = lo;
    } else if (i < PW_EMB + 2 * PW_REL) {
        int r = i - PW_EMB - PW_REL;
        int l0 = r / (128 * 128), rem = r % (128 * 128);
        int k = rem / 128, n = rem % 128;
        __nv_bfloat16 h, lo;
        split2(root_w[r], h, lo);
        owh[(size_t)l0 * 128 * 128 + n * 128 + k] = h;
        owl[(size_t)l0 * 128 * 128 + n * 128 + k] = lo;
    } else {
        // head: packed W [128,64] where col c<32 -> head_w[k][c], else head_w[128+k][c-32]
        // store ^T split: hw[c*128 + k]
        int r = i - PW_EMB - 2 * PW_REL;   // 0..8191
        int c = r / 128, k = r % 128;
        float v = (c < 32) ? head_w[k * CLS + c] : head_w[(128 + k) * CLS + (c - 32)];
        __nv_bfloat16 h, lo;
        split2(v, h, lo);
        hwh[c * 128 + k] = h;
        hwl[c * 128 + k] = lo;
    }
}

// ---------------------------------------------------------------------------
// CSR construction (blocked scan)
// ---------------------------------------------------------------------------
__global__ void zero_off_kernel(int* __restrict__ off)
{
    int i = blockIdx.x * blockDim.x + threadIdx.x;
    if (i <= NN) off[i] = 0;
}
__global__ void hist_kernel(const int* __restrict__ ei, int* __restrict__ off)
{
    int e = blockIdx.x * blockDim.x + threadIdx.x;
    if (e >= NE) return;
    atomicAdd(&off[ei[NE + e] + 1], 1);
}
__global__ void __launch_bounds__(SCAN_BLK)
scan_blk(int* __restrict__ off, int* __restrict__ bsum)
{
    __shared__ int s[SCAN_BLK];
    const int tid = threadIdx.x;
    const int i = blockIdx.x * SCAN_BLK + tid;
    int v = (i < SCAN_N) ? off[i] : 0;
    s[tid] = v;
    __syncthreads();
#pragma unroll
    for (int d = 1; d < SCAN_BLK; d <<= 1) {
        int t = (tid >= d) ? s[tid - d] : 0;
        __syncthreads();
        s[tid] += t;
        __syncthreads();
    }
    if (i < SCAN_N) off[i] = s[tid];
    if (tid == SCAN_BLK - 1) bsum[blockIdx.x] = s[tid];
}
__global__ void __launch_bounds__(128)
scan_bsum(int* __restrict__ bsum)
{
    __shared__ int s[128];
    const int tid = threadIdx.x;
    int v = (tid < SCAN_NB) ? bsum[tid] : 0;
    s[tid] = v;
    __syncthreads();
#pragma unroll
    for (int d = 1; d < 128; d <<= 1) {
        int t = (tid >= d) ? s[tid - d] : 0;
        __syncthreads();
        s[tid] += t;
        __syncthreads();
    }
    if (tid < SCAN_NB) bsum[tid] = s[tid] - v;
}
__global__ void __launch_bounds__(SCAN_BLK)
scan_add(int* __restrict__ off, const int* __restrict__ bsum, int* __restrict__ cur)
{
    const int i = blockIdx.x * SCAN_BLK + threadIdx.x;
    if (i < SCAN_N) {
        int v = off[i] + bsum[blockIdx.x];
        off[i] = v;
        if (i < NN) cur[i] = v;
    }
}
__global__ void fill_kernel(const int* __restrict__ ei, int* __restrict__ cur,
                            int* __restrict__ csr)
{
    int e = blockIdx.x * blockDim.x + threadIdx.x;
    if (e >= NE) return;
    int p = atomicAdd(&cur[ei[NE + e]], 1);
    csr[p] = ei[e];
}

// ---------------------------------------------------------------------------
__global__ void edge_out_kernel(const float* __restrict__ fg,
                                const int* __restrict__ ei,
                                const float* __restrict__ head_b,
                                float* __restrict__ out)
{
    int warp = (blockIdx.x * blockDim.x + threadIdx.x) >> 5;
    int lane = threadIdx.x & 31;
    if (warp >= NE) return;
    int src = ei[warp];
    int dst = ei[NE + warp];
    float v = fg[(size_t)src * 64 + lane] + fg[(size_t)dst * 64 + 32 + lane] + head_b[lane];
    out[(size_t)warp * CLS + lane] = v;
}

// ---------------------------------------------------------------------------
extern "C" void kernel_launch(void* const* d_in, const int* in_sizes, int n_in,
                              void* d_out, int out_size)
{
    const float* obj    = (const float*)d_in[0];
    const int*   ei     = (const int*)d_in[1];   // int32 (JAX x64 disabled)
    const float* emb_w  = (const float*)d_in[2];
    const float* emb_b  = (const float*)d_in[3];
    const float* rel_w  = (const float*)d_in[4];
    const float* rel_b  = (const float*)d_in[5];
    const float* root_w = (const float*)d_in[6];
    const float* head_w = (const float*)d_in[7];
    const float* head_b = (const float*)d_in[8];
    float*       out    = (float*)d_out;

    float *yA, *zA, *yB, *zB, *fg;
    int *off, *cur, *csr, *bsum;
    __nv_bfloat16 *xh, *xl, *ewh, *ewl, *rwh, *rwl, *owh, *owl, *hwh, *hwl;
    cudaGetSymbolAddress((void**)&yA,   g_yA);
    cudaGetSymbolAddress((void**)&zA,   g_zA);
    cudaGetSymbolAddress((void**)&yB,   g_yB);
    cudaGetSymbolAddress((void**)&zB,   g_zB);
    cudaGetSymbolAddress((void**)&fg,   g_fg);
    cudaGetSymbolAddress((void**)&off,  g_off);
    cudaGetSymbolAddress((void**)&cur,  g_cur);
    cudaGetSymbolAddress((void**)&csr,  g_csr);
    cudaGetSymbolAddress((void**)&bsum, g_bsum);
    cudaGetSymbolAddress((void**)&xh,   g_xh);
    cudaGetSymbolAddress((void**)&xl,   g_xl);
    cudaGetSymbolAddress((void**)&ewh,  g_ewh);
    cudaGetSymbolAddress((void**)&ewl,  g_ewl);
    cudaGetSymbolAddress((void**)&rwh,  g_rwh);
    cudaGetSymbolAddress((void**)&rwl,  g_rwl);
    cudaGetSymbolAddress((void**)&owh,  g_owh);
    cudaGetSymbolAddress((void**)&owl,  g_owl);
    cudaGetSymbolAddress((void**)&hwh,  g_hwh);
    cudaGetSymbolAddress((void**)&hwl,  g_hwl);

    cudaFuncSetAttribute(gemm_emb,         cudaFuncAttributeMaxDynamicSharedMemorySize, GSM_SIZE);
    cudaFuncSetAttribute(gemm_layer0,      cudaFuncAttributeMaxDynamicSharedMemorySize, LSM_SIZE);
    cudaFuncSetAttribute(gemm_layer_fused, cudaFuncAttributeMaxDynamicSharedMemorySize, LSM_SIZE);
    cudaFuncSetAttribute(gemm_head_fused,  cudaFuncAttributeMaxDynamicSharedMemorySize, HSM_SIZE);

    static cudaStream_t s_csr = nullptr;
    static cudaEvent_t  ev_fork = nullptr, ev_csr = nullptr;
    if (!s_csr) {
        cudaStreamCreateWithFlags(&s_csr, cudaStreamNonBlocking);
        cudaEventCreateWithFlags(&ev_fork, cudaEventDisableTiming);
        cudaEventCreateWithFlags(&ev_csr,  cudaEventDisableTiming);
    }

    const int gemm_gx   = (NN + 127) / 128;        // 391
    const int ne_blocks = (NE + 255) / 256;
    const int warp_blocks = (NE * 32 + 255) / 256;

    // fork: CSR chain (independent)
    cudaEventRecord(ev_fork, 0);
    cudaStreamWaitEvent(s_csr, ev_fork, 0);
    zero_off_kernel<<<(NN + 256) / 256, 256, 0, s_csr>>>(off);
    hist_kernel<<<ne_blocks, 256, 0, s_csr>>>(ei, off);
    scan_blk<<<SCAN_NB, SCAN_BLK, 0, s_csr>>>(off, bsum);
    scan_bsum<<<1, 128, 0, s_csr>>>(bsum);
    scan_add<<<SCAN_NB, SCAN_BLK, 0, s_csr>>>(off, bsum, cur);
    fill_kernel<<<ne_blocks, 256, 0, s_csr>>>(ei, cur, csr);
    cudaEventRecord(ev_csr, s_csr);

    // main: prep -> emb -> layer0 GEMM
    prep_weights<<<(PW_TOTAL + 255) / 256, 256>>>(
        emb_w, rel_w, root_w, head_w, ewh, ewl, rwh, rwl, owh, owl, hwh, hwl);

    gemm_emb<<<gemm_gx, 256, GSM_SIZE>>>(obj, ewh, ewl, emb_b, xh, xl);

    gemm_layer0<<<gemm_gx, 256, LSM_SIZE>>>(
        xh, xl, rwh, rwl, owh, owl, rel_b, yA, zA);

    // join: fused kernels need CSR
    cudaStreamWaitEvent(0, ev_csr, 0);

    // layer 1: agg(yA,zA) -> GEMM -> yB,zB
    gemm_layer_fused<<<gemm_gx, 256, LSM_SIZE>>>(
        (const float4*)yA, (const float4*)zA, off, csr,
        rwh + 128 * 128, rwl + 128 * 128,
        owh + 128 * 128, owl + 128 * 128,
        rel_b + 128, yB, zB);

    // layer 2: agg(yB,zB) -> GEMM -> yA,zA
    gemm_layer_fused<<<gemm_gx, 256, LSM_SIZE>>>(
        (const float4*)yB, (const float4*)zB, off, csr,
        rwh + 2 * 128 * 128, rwl + 2 * 128 * 128,
        owh + 2 * 128 * 128, owl + 2 * 128 * 128,
        rel_b + 2 * 128, yA, zA);

    // head: agg(yA,zA) -> head GEMM -> fg
    gemm_head_fused<<<gemm_gx, 256, HSM_SIZE>>>(
        (const float4*)yA, (const float4*)zA, off, csr, hwh, hwl, fg);

    edge_out_kernel<<<warp_blocks, 256>>>(fg, ei, head_b, out);
}

// round 17
// speedup vs baseline: 1.4808x; 1.4808x over previous
#include <cuda_runtime.h>
#include <cuda_bf16.h>
#include <cstdint>

constexpr int NN   = 50000;   // nodes
constexpr int NE   = 600000;  // edges
constexpr int FEAT = 256;
constexpr int HID  = 128;
constexpr int CLS  = 32;
constexpr int NLAYERS = 3;

// ---------------- device scratch (no allocs allowed) ----------------
__device__ float g_y [NN * HID];
__device__ float g_z [NN * HID];
__device__ float g_fg[NN * 64];
__device__ int   g_off[NN + 1];
__device__ int   g_cur[NN];
__device__ int   g_csr[NE];

constexpr int SCAN_BLK = 512;
constexpr int SCAN_N   = NN + 1;
constexpr int SCAN_NB  = (SCAN_N + SCAN_BLK - 1) / SCAN_BLK;      // 98
__device__ int g_bsum[SCAN_NB];

__device__ __nv_bfloat16 g_xh[NN * HID];
__device__ __nv_bfloat16 g_xl[NN * HID];
__device__ __nv_bfloat16 g_ewh[128 * 256];
__device__ __nv_bfloat16 g_ewl[128 * 256];
__device__ __nv_bfloat16 g_rwh[3 * 128 * 128];
__device__ __nv_bfloat16 g_rwl[3 * 128 * 128];
__device__ __nv_bfloat16 g_owh[3 * 128 * 128];
__device__ __nv_bfloat16 g_owl[3 * 128 * 128];
__device__ __nv_bfloat16 g_hwh[64 * 128];     // head weights packed, ^T, split
__device__ __nv_bfloat16 g_hwl[64 * 128];

// ---------------- helpers ----------------
__device__ __forceinline__ uint32_t smem_u32(const void* p) {
    uint32_t a;
    asm("{ .reg .u64 t; cvta.to.shared.u64 t, %1; cvt.u32.u64 %0, t; }" : "=r"(a) : "l"(p));
    return a;
}
__device__ __forceinline__ void split2(float v, __nv_bfloat16& h, __nv_bfloat16& l) {
    h = __float2bfloat16_rn(v);
    l = __float2bfloat16_rn(v - __bfloat162float(h));
}
__device__ __forceinline__ void ldsm4(uint32_t* r, uint32_t addr) {
    asm volatile("ldmatrix.sync.aligned.m8n8.x4.shared.b16 {%0,%1,%2,%3}, [%4];"
        : "=r"(r[0]), "=r"(r[1]), "=r"(r[2]), "=r"(r[3]) : "r"(addr));
}
__device__ __forceinline__ void ldsm2(uint32_t* r, uint32_t addr) {
    asm volatile("ldmatrix.sync.aligned.m8n8.x2.shared.b16 {%0,%1}, [%2];"
        : "=r"(r[0]), "=r"(r[1]) : "r"(addr));
}
__device__ __forceinline__ void mma_bf16(float* c, const uint32_t* a, const uint32_t* b) {
    asm volatile(
        "mma.sync.aligned.m16n8k16.row.col.f32.bf16.bf16.f32 "
        "{%0,%1,%2,%3}, {%4,%5,%6,%7}, {%8,%9}, {%0,%1,%2,%3};"
        : "+f"(c[0]), "+f"(c[1]), "+f"(c[2]), "+f"(c[3])
        : "r"(a[0]), "r"(a[1]), "r"(a[2]), "r"(a[3]), "r"(b[0]), "r"(b[1]));
}

constexpr int KCH  = 128;
constexpr int KST  = KCH + 8;
constexpr int TILE_ELEMS = 128 * KST;
constexpr int TILE_BYTES = TILE_ELEMS * 2;
constexpr int WTILE_ELEMS = 64 * KST;
constexpr int GSM_SIZE = 4 * TILE_BYTES;
constexpr int LSM_SIZE = 6 * TILE_BYTES;
constexpr int HSM_SIZE = 2 * TILE_BYTES + 2 * WTILE_ELEMS * 2;   // ~104KB

// ---------------------------------------------------------------------------
// Fused layer GEMM (split-precision bf16 mma.sync):
//   Y = X @ rel_w; Z = X @ root_w + bias
// ---------------------------------------------------------------------------
__global__ void __launch_bounds__(256)
gemm_layer(const __nv_bfloat16* __restrict__ Ah, const __nv_bfloat16* __restrict__ Al,
           const __nv_bfloat16* __restrict__ Rh, const __nv_bfloat16* __restrict__ Rl,
           const __nv_bfloat16* __restrict__ Oh, const __nv_bfloat16* __restrict__ Ol,
           const float* __restrict__ bias,
           float* __restrict__ outY, float* __restrict__ outZ)
{
    extern __shared__ __nv_bfloat16 sm[];
    __nv_bfloat16* sAh = sm;
    __nv_bfloat16* sAl = sm + TILE_ELEMS;
    __nv_bfloat16* sRh = sm + 2 * TILE_ELEMS;
    __nv_bfloat16* sRl = sm + 3 * TILE_ELEMS;
    __nv_bfloat16* sOh = sm + 4 * TILE_ELEMS;
    __nv_bfloat16* sOl = sm + 5 * TILE_ELEMS;

    const int tid  = threadIdx.x;
    const int warp = tid >> 5, lane = tid & 31;
    const int row0 = blockIdx.x * 128;
    const int rows = NN - row0;
    const int wm = (warp >> 1) * 32;
    const int wn = (warp & 1) * 64;

#pragma unroll
    for (int v = 0; v < 8; v++) {
        int i = tid + v * 256;
        int r = i >> 4, c = (i & 15) * 8;
        uint4 t = make_uint4(0u, 0u, 0u, 0u);
        uint4 u = make_uint4(0u, 0u, 0u, 0u);
        if (r < rows) {
            t = *(const uint4*)(Ah + (size_t)(row0 + r) * 128 + c);
            u = *(const uint4*)(Al + (size_t)(row0 + r) * 128 + c);
        }
        *(uint4*)(sAh + r * KST + c) = t;
        *(uint4*)(sAl + r * KST + c) = u;
        *(uint4*)(sRh + r * KST + c) = *(const uint4*)(Rh + (size_t)r * 128 + c);
        *(uint4*)(sRl + r * KST + c) = *(const uint4*)(Rl + (size_t)r * 128 + c);
        *(uint4*)(sOh + r * KST + c) = *(const uint4*)(Oh + (size_t)r * 128 + c);
        *(uint4*)(sOl + r * KST + c) = *(const uint4*)(Ol + (size_t)r * 128 + c);
    }
    __syncthreads();

    float accY[2][8][4], accZ[2][8][4];
#pragma unroll
    for (int m = 0; m < 2; m++)
#pragma unroll
        for (int nt = 0; nt < 8; nt++)
#pragma unroll
            for (int j = 0; j < 4; j++) { accY[m][nt][j] = 0.f; accZ[m][nt][j] = 0.f; }

    const uint32_t uAh = smem_u32(sAh), uAl = smem_u32(sAl);
    const uint32_t uRh = smem_u32(sRh), uRl = smem_u32(sRl);
    const uint32_t uOh = smem_u32(sOh), uOl = smem_u32(sOl);

    const int rin  = lane & 7;
    const int quad = lane >> 3;
    const int a_radd = (quad & 1) * 8 + rin;
    const int a_cadd = (quad >> 1) * 16;
    const int b_l16  = lane & 15;
    const int b_radd = b_l16 & 7;
    const int b_cadd = (b_l16 >> 3) * 16;

#pragma unroll
    for (int ks = 0; ks < 8; ks++) {
        uint32_t afh[2][4], afl[2][4];
#pragma unroll
        for (int m = 0; m < 2; m++) {
            uint32_t off = (uint32_t)(wm + m * 16 + a_radd) * (KST * 2)
                         + (uint32_t)(ks * 32 + a_cadd);
            ldsm4(afh[m], uAh + off);
            ldsm4(afl[m], uAl + off);
        }
#pragma unroll
        for (int nt = 0; nt < 8; nt++) {
            uint32_t off = (uint32_t)(wn + nt * 8 + b_radd) * (KST * 2)
                         + (uint32_t)(ks * 32 + b_cadd);
            uint32_t rh[2], rl[2], oh[2], ol[2];
            ldsm2(rh, uRh + off);
            ldsm2(rl, uRl + off);
            ldsm2(oh, uOh + off);
            ldsm2(ol, uOl + off);
#pragma unroll
            for (int m = 0; m < 2; m++) {
                mma_bf16(accY[m][nt], afh[m], rh);
                mma_bf16(accY[m][nt], afl[m], rh);
                mma_bf16(accY[m][nt], afh[m], rl);
                mma_bf16(accZ[m][nt], afh[m], oh);
                mma_bf16(accZ[m][nt], afl[m], oh);
                mma_bf16(accZ[m][nt], afh[m], ol);
            }
        }
    }

    const int g = lane >> 2, tig = lane & 3;
#pragma unroll
    for (int m = 0; m < 2; m++) {
#pragma unroll
        for (int nt = 0; nt < 8; nt++) {
            int col = wn + nt * 8 + 2 * tig;
            int r1 = row0 + wm + m * 16 + g;
            int r2 = r1 + 8;
            float b0 = bias[col], b1 = bias[col + 1];
            if (r1 < NN) {
                *(float2*)(outY + (size_t)r1 * 128 + col) =
                    make_float2(accY[m][nt][0], accY[m][nt][1]);
                *(float2*)(outZ + (size_t)r1 * 128 + col) =
                    make_float2(accZ[m][nt][0] + b0, accZ[m][nt][1] + b1);
            }
            if (r2 < NN) {
                *(float2*)(outY + (size_t)r2 * 128 + col) =
                    make_float2(accY[m][nt][2], accY[m][nt][3]);
                *(float2*)(outZ + (size_t)r2 * 128 + col) =
                    make_float2(accZ[m][nt][2] + b0, accZ[m][nt][3] + b1);
            }
        }
    }
}

// ---------------------------------------------------------------------------
// Embedding GEMM (split bf16 mma.sync, K=256 in 2 chunks)
// ---------------------------------------------------------------------------
__global__ void __launch_bounds__(256)
gemm_emb(const float* __restrict__ A,
         const __nv_bfloat16* __restrict__ Bh, const __nv_bfloat16* __restrict__ Bl,
         const float* __restrict__ bias,
         __nv_bfloat16* __restrict__ outH, __nv_bfloat16* __restrict__ outL)
{
    extern __shared__ __nv_bfloat16 sm[];
    __nv_bfloat16* sAh = sm;
    __nv_bfloat16* sAl = sm + TILE_ELEMS;
    __nv_bfloat16* sBh = sm + 2 * TILE_ELEMS;
    __nv_bfloat16* sBl = sm + 3 * TILE_ELEMS;

    const int tid  = threadIdx.x;
    const int warp = tid >> 5, lane = tid & 31;
    const int row0 = blockIdx.x * 128;
    const int rows = NN - row0;
    const int wm = (warp >> 1) * 32;
    const int wn = (warp & 1) * 64;
    const int K = 256;

    float acc[2][8][4];
#pragma unroll
    for (int m = 0; m < 2; m++)
#pragma unroll
        for (int nt = 0; nt < 8; nt++)
#pragma unroll
            for (int j = 0; j < 4; j++) acc[m][nt][j] = 0.f;

    const uint32_t uAh = smem_u32(sAh), uAl = smem_u32(sAl);
    const uint32_t uBh = smem_u32(sBh), uBl = smem_u32(sBl);

    const int rin  = lane & 7;
    const int quad = lane >> 3;
    const int a_radd = (quad & 1) * 8 + rin;
    const int a_cadd = (quad >> 1) * 16;
    const int b_l16  = lane & 15;
    const int b_radd = b_l16 & 7;
    const int b_cadd = (b_l16 >> 3) * 16;

    for (int kc = 0; kc < K; kc += KCH) {
        if (kc) __syncthreads();
#pragma unroll
        for (int v = 0; v < 16; v++) {
            int i = tid + v * 256;
            int r = i >> 5, c4 = (i & 31) * 4;
            float4 t = make_float4(0.f, 0.f, 0.f, 0.f);
            if (r < rows)
                t = *(const float4*)(A + (size_t)(row0 + r) * K + kc + c4);
            __nv_bfloat16 h0, l0, h1, l1, h2, l2, h3, l3;
            split2(t.x, h0, l0); split2(t.y, h1, l1);
            split2(t.z, h2, l2); split2(t.w, h3, l3);
            __nv_bfloat162 ha, hb, la, lb;
            ha.x = h0; ha.y = h1; hb.x = h2; hb.y = h3;
            la.x = l0; la.y = l1; lb.x = l2; lb.y = l3;
            *(__nv_bfloat162*)(sAh + r * KST + c4)     = ha;
            *(__nv_bfloat162*)(sAh + r * KST + c4 + 2) = hb;
            *(__nv_bfloat162*)(sAl + r * KST + c4)     = la;
            *(__nv_bfloat162*)(sAl + r * KST + c4 + 2) = lb;
        }
#pragma unroll
        for (int v = 0; v < 8; v++) {
            int i = tid + v * 256;
            int r = i >> 4, c = (i & 15) * 8;
            *(uint4*)(sBh + r * KST + c) = *(const uint4*)(Bh + (size_t)r * K + kc + c);
            *(uint4*)(sBl + r * KST + c) = *(const uint4*)(Bl + (size_t)r * K + kc + c);
        }
        __syncthreads();

#pragma unroll
        for (int ks = 0; ks < 8; ks++) {
            uint32_t afh[2][4], afl[2][4];
#pragma unroll
            for (int m = 0; m < 2; m++) {
                uint32_t off = (uint32_t)(wm + m * 16 + a_radd) * (KST * 2)
                             + (uint32_t)(ks * 32 + a_cadd);
                ldsm4(afh[m], uAh + off);
                ldsm4(afl[m], uAl + off);
            }
#pragma unroll
            for (int nt = 0; nt < 8; nt++) {
                uint32_t bh[2], bl[2];
                uint32_t off = (uint32_t)(wn + nt * 8 + b_radd) * (KST * 2)
                             + (uint32_t)(ks * 32 + b_cadd);
                ldsm2(bh, uBh + off);
                ldsm2(bl, uBl + off);
#pragma unroll
                for (int m = 0; m < 2; m++) {
                    mma_bf16(acc[m][nt], afh[m], bh);
                    mma_bf16(acc[m][nt], afl[m], bh);
                    mma_bf16(acc[m][nt], afh[m], bl);
                }
            }
        }
    }

    const int g = lane >> 2, tig = lane & 3;
#pragma unroll
    for (int m = 0; m < 2; m++) {
#pragma unroll
        for (int nt = 0; nt < 8; nt++) {
            int col = wn + nt * 8 + 2 * tig;
            int r1 = row0 + wm + m * 16 + g;
            int r2 = r1 + 8;
            float b0 = bias[col], b1 = bias[col + 1];
            float v00 = fmaxf(acc[m][nt][0] + b0, 0.f), v01 = fmaxf(acc[m][nt][1] + b1, 0.f);
            float v10 = fmaxf(acc[m][nt][2] + b0, 0.f), v11 = fmaxf(acc[m][nt][3] + b1, 0.f);
            __nv_bfloat16 h0, l0, h1, l1;
            if (r1 < NN) {
                split2(v00, h0, l0); split2(v01, h1, l1);
                __nv_bfloat162 hh; hh.x = h0; hh.y = h1;
                __nv_bfloat162 ll; ll.x = l0; ll.y = l1;
                *(__nv_bfloat162*)(outH + (size_t)r1 * 128 + col) = hh;
                *(__nv_bfloat162*)(outL + (size_t)r1 * 128 + col) = ll;
            }
            if (r2 < NN) {
                split2(v10, h0, l0); split2(v11, h1, l1);
                __nv_bfloat162 hh; hh.x = h0; hh.y = h1;
                __nv_bfloat162 ll; ll.x = l0; ll.y = l1;
                *(__nv_bfloat162*)(outH + (size_t)r2 * 128 + col) = hh;
                *(__nv_bfloat162*)(outL + (size_t)r2 * 128 + col) = ll;
            }
        }
    }
}

// ---------------------------------------------------------------------------
// Head GEMM (split bf16 mma.sync, N=64): fg = X @ packedW
// A read from global split bf16 (xh, xl).
// ---------------------------------------------------------------------------
__global__ void __launch_bounds__(256)
gemm_head_bf16(const __nv_bfloat16* __restrict__ Ah, const __nv_bfloat16* __restrict__ Al,
               const __nv_bfloat16* __restrict__ Wh, const __nv_bfloat16* __restrict__ Wl,
               float* __restrict__ fg)
{
    extern __shared__ __nv_bfloat16 sm[];
    __nv_bfloat16* sAh = sm;
    __nv_bfloat16* sAl = sm + TILE_ELEMS;
    __nv_bfloat16* sWh = sm + 2 * TILE_ELEMS;
    __nv_bfloat16* sWl = sm + 2 * TILE_ELEMS + WTILE_ELEMS;

    const int tid = threadIdx.x;
    const int warp = tid >> 5, lane = tid & 31;
    const int row0 = blockIdx.x * 128;
    const int rows = NN - row0;

    // stage A [128,128] split
#pragma unroll
    for (int v = 0; v < 8; v++) {
        int i = tid + v * 256;
        int r = i >> 4, c = (i & 15) * 8;
        uint4 t = make_uint4(0u, 0u, 0u, 0u);
        uint4 u = make_uint4(0u, 0u, 0u, 0u);
        if (r < rows) {
            t = *(const uint4*)(Ah + (size_t)(row0 + r) * 128 + c);
            u = *(const uint4*)(Al + (size_t)(row0 + r) * 128 + c);
        }
        *(uint4*)(sAh + r * KST + c) = t;
        *(uint4*)(sAl + r * KST + c) = u;
    }
    // stage head weights [64,128]
#pragma unroll
    for (int v = 0; v < 4; v++) {
        int i = tid + v * 256;
        int r = i >> 4, c = (i & 15) * 8;
        *(uint4*)(sWh + r * KST + c) = *(const uint4*)(Wh + (size_t)r * 128 + c);
        *(uint4*)(sWl + r * KST + c) = *(const uint4*)(Wl + (size_t)r * 128 + c);
    }
    __syncthreads();

    const int wm = (warp >> 1) * 32;
    const int wn = (warp & 1) * 32;    // N=64 split over 2 warp columns

    float acc[2][4][4];
#pragma unroll
    for (int m = 0; m < 2; m++)
#pragma unroll
        for (int nt = 0; nt < 4; nt++)
#pragma unroll
            for (int j = 0; j < 4; j++) acc[m][nt][j] = 0.f;

    const uint32_t uAh = smem_u32(sAh), uAl = smem_u32(sAl);
    const uint32_t uWh = smem_u32(sWh), uWl = smem_u32(sWl);

    const int rin  = lane & 7;
    const int quad = lane >> 3;
    const int a_radd = (quad & 1) * 8 + rin;
    const int a_cadd = (quad >> 1) * 16;
    const int b_l16  = lane & 15;
    const int b_radd = b_l16 & 7;
    const int b_cadd = (b_l16 >> 3) * 16;

#pragma unroll
    for (int ks = 0; ks < 8; ks++) {
        uint32_t afh[2][4], afl[2][4];
#pragma unroll
        for (int m = 0; m < 2; m++) {
            uint32_t off2 = (uint32_t)(wm + m * 16 + a_radd) * (KST * 2)
                          + (uint32_t)(ks * 32 + a_cadd);
            ldsm4(afh[m], uAh + off2);
            ldsm4(afl[m], uAl + off2);
        }
#pragma unroll
        for (int nt = 0; nt < 4; nt++) {
            uint32_t off2 = (uint32_t)(wn + nt * 8 + b_radd) * (KST * 2)
                          + (uint32_t)(ks * 32 + b_cadd);
            uint32_t wh[2], wl[2];
            ldsm2(wh, uWh + off2);
            ldsm2(wl, uWl + off2);
#pragma unroll
            for (int m = 0; m < 2; m++) {
                mma_bf16(acc[m][nt], afh[m], wh);
                mma_bf16(acc[m][nt], afl[m], wh);
                mma_bf16(acc[m][nt], afh[m], wl);
            }
        }
    }

    const int g = lane >> 2, tig = lane & 3;
#pragma unroll
    for (int m = 0; m < 2; m++) {
#pragma unroll
        for (int nt = 0; nt < 4; nt++) {
            int col = wn + nt * 8 + 2 * tig;
            int r1 = row0 + wm + m * 16 + g;
            int r2 = r1 + 8;
            if (r1 < NN)
                *(float2*)(fg + (size_t)r1 * 64 + col) = make_float2(acc[m][nt][0], acc[m][nt][1]);
            if (r2 < NN)
                *(float2*)(fg + (size_t)r2 * 64 + col) = make_float2(acc[m][nt][2], acc[m][nt][3]);
        }
    }
}

// ---------------------------------------------------------------------------
// One-shot weight prep (head weights -> packed^T split bf16)
// ---------------------------------------------------------------------------
constexpr int PW_EMB  = 256 * 128;
constexpr int PW_REL  = 3 * 128 * 128;
constexpr int PW_HEAD = 64 * 128;
constexpr int PW_TOTAL = PW_EMB + 2 * PW_REL + PW_HEAD;

__global__ void prep_weights(const float* __restrict__ emb_w,
                             const float* __restrict__ rel_w,
                             const float* __restrict__ root_w,
                             const float* __restrict__ head_w,
                             __nv_bfloat16* __restrict__ ewh, __nv_bfloat16* __restrict__ ewl,
                             __nv_bfloat16* __restrict__ rwh, __nv_bfloat16* __restrict__ rwl,
                             __nv_bfloat16* __restrict__ owh, __nv_bfloat16* __restrict__ owl,
                             __nv_bfloat16* __restrict__ hwh, __nv_bfloat16* __restrict__ hwl)
{
    int i = blockIdx.x * blockDim.x + threadIdx.x;
    if (i >= PW_TOTAL) return;
    if (i < PW_EMB) {
        int k = i / 128, n = i % 128;
        __nv_bfloat16 h, l;
        split2(emb_w[i], h, l);
        ewh[n * 256 + k] = h;
        ewl[n * 256 + k] = l;
    } else if (i < PW_EMB + PW_REL) {
        int r = i - PW_EMB;
        int l0 = r / (128 * 128), rem = r % (128 * 128);
        int k = rem / 128, n = rem % 128;
        __nv_bfloat16 h, lo;
        split2(rel_w[r], h, lo);
        rwh[(size_t)l0 * 128 * 128 + n * 128 + k] = h;
        rwl[(size_t)l0 * 128 * 128 + n * 128 + k] = lo;
    } else if (i < PW_EMB + 2 * PW_REL) {
        int r = i - PW_EMB - PW_REL;
        int l0 = r / (128 * 128), rem = r % (128 * 128);
        int k = rem / 128, n = rem % 128;
        __nv_bfloat16 h, lo;
        split2(root_w[r], h, lo);
        owh[(size_t)l0 * 128 * 128 + n * 128 + k] = h;
        owl[(size_t)l0 * 128 * 128 + n * 128 + k] = lo;
    } else {
        int r = i - PW_EMB - 2 * PW_REL;   // 0..8191
        int c = r / 128, k = r % 128;
        float v = (c < 32) ? head_w[k * CLS + c] : head_w[(128 + k) * CLS + (c - 32)];
        __nv_bfloat16 h, lo;
        split2(v, h, lo);
        hwh[c * 128 + k] = h;
        hwl[c * 128 + k] = lo;
    }
}

// ---------------------------------------------------------------------------
// CSR construction (blocked scan)
// ---------------------------------------------------------------------------
__global__ void zero_off_kernel(int* __restrict__ off)
{
    int i = blockIdx.x * blockDim.x + threadIdx.x;
    if (i <= NN) off[i] = 0;
}
__global__ void hist_kernel(const int* __restrict__ ei, int* __restrict__ off)
{
    int e = blockIdx.x * blockDim.x + threadIdx.x;
    if (e >= NE) return;
    atomicAdd(&off[ei[NE + e] + 1], 1);
}
__global__ void __launch_bounds__(SCAN_BLK)
scan_blk(int* __restrict__ off, int* __restrict__ bsum)
{
    __shared__ int s[SCAN_BLK];
    const int tid = threadIdx.x;
    const int i = blockIdx.x * SCAN_BLK + tid;
    int v = (i < SCAN_N) ? off[i] : 0;
    s[tid] = v;
    __syncthreads();
#pragma unroll
    for (int d = 1; d < SCAN_BLK; d <<= 1) {
        int t = (tid >= d) ? s[tid - d] : 0;
        __syncthreads();
        s[tid] += t;
        __syncthreads();
    }
    if (i < SCAN_N) off[i] = s[tid];
    if (tid == SCAN_BLK - 1) bsum[blockIdx.x] = s[tid];
}
__global__ void __launch_bounds__(128)
scan_bsum(int* __restrict__ bsum)
{
    __shared__ int s[128];
    const int tid = threadIdx.x;
    int v = (tid < SCAN_NB) ? bsum[tid] : 0;
    s[tid] = v;
    __syncthreads();
#pragma unroll
    for (int d = 1; d < 128; d <<= 1) {
        int t = (tid >= d) ? s[tid - d] : 0;
        __syncthreads();
        s[tid] += t;
        __syncthreads();
    }
    if (tid < SCAN_NB) bsum[tid] = s[tid] - v;
}
__global__ void __launch_bounds__(SCAN_BLK)
scan_add(int* __restrict__ off, const int* __restrict__ bsum, int* __restrict__ cur)
{
    const int i = blockIdx.x * SCAN_BLK + threadIdx.x;
    if (i < SCAN_N) {
        int v = off[i] + bsum[blockIdx.x];
        off[i] = v;
        if (i < NN) cur[i] = v;
    }
}
__global__ void fill_kernel(const int* __restrict__ ei, int* __restrict__ cur,
                            int* __restrict__ csr)
{
    int e = blockIdx.x * blockDim.x + threadIdx.x;
    if (e >= NE) return;
    int p = atomicAdd(&cur[ei[NE + e]], 1);
    csr[p] = ei[e];
}

// ---------------------------------------------------------------------------
// Aggregate: x(split) = relu(z[n] + sum y[src])   (warp per node, 4-way unroll)
// ---------------------------------------------------------------------------
__device__ __forceinline__ float4 agg_node(const float4* __restrict__ y4,
                                           const float4* __restrict__ z4,
                                           const int* __restrict__ csr,
                                           int node, int lane, int s, int e)
{
    float4 acc = z4[(size_t)node * 32 + lane];
    for (int b = s; b < e; b += 32) {
        int idx = b + lane;
        int mysrc = (idx < e) ? csr[idx] : 0;
        int cnt = e - b; if (cnt > 32) cnt = 32;
        int j = 0;
        for (; j + 4 <= cnt; j += 4) {
            int s0 = __shfl_sync(0xffffffffu, mysrc, j);
            int s1 = __shfl_sync(0xffffffffu, mysrc, j + 1);
            int s2 = __shfl_sync(0xffffffffu, mysrc, j + 2);
            int s3 = __shfl_sync(0xffffffffu, mysrc, j + 3);
            float4 v0 = y4[(size_t)s0 * 32 + lane];
            float4 v1 = y4[(size_t)s1 * 32 + lane];
            float4 v2 = y4[(size_t)s2 * 32 + lane];
            float4 v3 = y4[(size_t)s3 * 32 + lane];
            acc.x += (v0.x + v1.x) + (v2.x + v3.x);
            acc.y += (v0.y + v1.y) + (v2.y + v3.y);
            acc.z += (v0.z + v1.z) + (v2.z + v3.z);
            acc.w += (v0.w + v1.w) + (v2.w + v3.w);
        }
        for (; j < cnt; j++) {
            int s0 = __shfl_sync(0xffffffffu, mysrc, j);
            float4 v0 = y4[(size_t)s0 * 32 + lane];
            acc.x += v0.x; acc.y += v0.y; acc.z += v0.z; acc.w += v0.w;
        }
    }
    acc.x = fmaxf(acc.x, 0.f); acc.y = fmaxf(acc.y, 0.f);
    acc.z = fmaxf(acc.z, 0.f); acc.w = fmaxf(acc.w, 0.f);
    return acc;
}

__global__ void aggregate_split_kernel(const float4* __restrict__ y4,
                                       const float4* __restrict__ z4,
                                       __nv_bfloat16* __restrict__ xh,
                                       __nv_bfloat16* __restrict__ xl,
                                       const int* __restrict__ off,
                                       const int* __restrict__ csr)
{
    int node = (blockIdx.x * blockDim.x + threadIdx.x) >> 5;
    int lane = threadIdx.x & 31;
    if (node >= NN) return;
    float4 acc = agg_node(y4, z4, csr, node, lane, off[node], off[node + 1]);
    __nv_bfloat16 h0, l0, h1, l1, h2, l2, h3, l3;
    split2(acc.x, h0, l0); split2(acc.y, h1, l1);
    split2(acc.z, h2, l2); split2(acc.w, h3, l3);
    __nv_bfloat162 ha, hb, la, lb;
    ha.x = h0; ha.y = h1; hb.x = h2; hb.y = h3;
    la.x = l0; la.y = l1; lb.x = l2; lb.y = l3;
    size_t base = (size_t)node * 128 + lane * 4;
    *(__nv_bfloat162*)(xh + base)     = ha;
    *(__nv_bfloat162*)(xh + base + 2) = hb;
    *(__nv_bfloat162*)(xl + base)     = la;
    *(__nv_bfloat162*)(xl + base + 2) = lb;
}

// ---------------------------------------------------------------------------
__global__ void edge_out_kernel(const float* __restrict__ fg,
                                const int* __restrict__ ei,
                                const float* __restrict__ head_b,
                                float* __restrict__ out)
{
    int warp = (blockIdx.x * blockDim.x + threadIdx.x) >> 5;
    int lane = threadIdx.x & 31;
    if (warp >= NE) return;
    int src = ei[warp];
    int dst = ei[NE + warp];
    float v = fg[(size_t)src * 64 + lane] + fg[(size_t)dst * 64 + 32 + lane] + head_b[lane];
    out[(size_t)warp * CLS + lane] = v;
}

// ---------------------------------------------------------------------------
extern "C" void kernel_launch(void* const* d_in, const int* in_sizes, int n_in,
                              void* d_out, int out_size)
{
    const float* obj    = (const float*)d_in[0];
    const int*   ei     = (const int*)d_in[1];   // int32 (JAX x64 disabled)
    const float* emb_w  = (const float*)d_in[2];
    const float* emb_b  = (const float*)d_in[3];
    const float* rel_w  = (const float*)d_in[4];
    const float* rel_b  = (const float*)d_in[5];
    const float* root_w = (const float*)d_in[6];
    const float* head_w = (const float*)d_in[7];
    const float* head_b = (const float*)d_in[8];
    float*       out    = (float*)d_out;

    float *y, *z, *fg;
    int *off, *cur, *csr, *bsum;
    __nv_bfloat16 *xh, *xl, *ewh, *ewl, *rwh, *rwl, *owh, *owl, *hwh, *hwl;
    cudaGetSymbolAddress((void**)&y,    g_y);
    cudaGetSymbolAddress((void**)&z,    g_z);
    cudaGetSymbolAddress((void**)&fg,   g_fg);
    cudaGetSymbolAddress((void**)&off,  g_off);
    cudaGetSymbolAddress((void**)&cur,  g_cur);
    cudaGetSymbolAddress((void**)&csr,  g_csr);
    cudaGetSymbolAddress((void**)&bsum, g_bsum);
    cudaGetSymbolAddress((void**)&xh,   g_xh);
    cudaGetSymbolAddress((void**)&xl,   g_xl);
    cudaGetSymbolAddress((void**)&ewh,  g_ewh);
    cudaGetSymbolAddress((void**)&ewl,  g_ewl);
    cudaGetSymbolAddress((void**)&rwh,  g_rwh);
    cudaGetSymbolAddress((void**)&rwl,  g_rwl);
    cudaGetSymbolAddress((void**)&owh,  g_owh);
    cudaGetSymbolAddress((void**)&owl,  g_owl);
    cudaGetSymbolAddress((void**)&hwh,  g_hwh);
    cudaGetSymbolAddress((void**)&hwl,  g_hwl);

    cudaFuncSetAttribute(gemm_emb,       cudaFuncAttributeMaxDynamicSharedMemorySize, GSM_SIZE);
    cudaFuncSetAttribute(gemm_layer,     cudaFuncAttributeMaxDynamicSharedMemorySize, LSM_SIZE);
    cudaFuncSetAttribute(gemm_head_bf16, cudaFuncAttributeMaxDynamicSharedMemorySize, HSM_SIZE);

    static cudaStream_t s_csr = nullptr;
    static cudaEvent_t  ev_fork = nullptr, ev_csr = nullptr;
    if (!s_csr) {
        cudaStreamCreateWithFlags(&s_csr, cudaStreamNonBlocking);
        cudaEventCreateWithFlags(&ev_fork, cudaEventDisableTiming);
        cudaEventCreateWithFlags(&ev_csr,  cudaEventDisableTiming);
    }

    const int gemm_gx   = (NN + 127) / 128;        // 391
    const int ne_blocks = (NE + 255) / 256;
    const int warp_blocks = (NE * 32 + 255) / 256;
    const int agg_blocks  = (NN * 32 + 255) / 256;

    // fork: CSR chain (independent)
    cudaEventRecord(ev_fork, 0);
    cudaStreamWaitEvent(s_csr, ev_fork, 0);
    zero_off_kernel<<<(NN + 256) / 256, 256, 0, s_csr>>>(off);
    hist_kernel<<<ne_blocks, 256, 0, s_csr>>>(ei, off);
    scan_blk<<<SCAN_NB, SCAN_BLK, 0, s_csr>>>(off, bsum);
    scan_bsum<<<1, 128, 0, s_csr>>>(bsum);
    scan_add<<<SCAN_NB, SCAN_BLK, 0, s_csr>>>(off, bsum, cur);
    fill_kernel<<<ne_blocks, 256, 0, s_csr>>>(ei, cur, csr);
    cudaEventRecord(ev_csr, s_csr);

    // main: prep -> emb -> layer0 GEMM
    prep_weights<<<(PW_TOTAL + 255) / 256, 256>>>(
        emb_w, rel_w, root_w, head_w, ewh, ewl, rwh, rwl, owh, owl, hwh, hwl);

    gemm_emb<<<gemm_gx, 256, GSM_SIZE>>>(obj, ewh, ewl, emb_b, xh, xl);

    gemm_layer<<<gemm_gx, 256, LSM_SIZE>>>(
        xh, xl, rwh, rwl, owh, owl, rel_b, y, z);

    // join: aggregates need CSR
    cudaStreamWaitEvent(0, ev_csr, 0);

    aggregate_split_kernel<<<agg_blocks, 256>>>(
        (const float4*)y, (const float4*)z, xh, xl, off, csr);

    for (int l = 1; l < NLAYERS; l++) {
        gemm_layer<<<gemm_gx, 256, LSM_SIZE>>>(
            xh, xl,
            rwh + (size_t)l * 128 * 128, rwl + (size_t)l * 128 * 128,
            owh + (size_t)l * 128 * 128, owl + (size_t)l * 128 * 128,
            rel_b + (size_t)l * 128, y, z);
        aggregate_split_kernel<<<agg_blocks, 256>>>(
            (const float4*)y, (const float4*)z, xh, xl, off, csr);
    }

    // head (split bf16 MMA) + edge output
    gemm_head_bf16<<<gemm_gx, 256, HSM_SIZE>>>(xh, xl, hwh, hwl, fg);
    edge_out_kernel<<<warp_blocks, 256>>>(fg, ei, head_b, out);
}